// round 8
// baseline (speedup 1.0000x reference)
#include <cuda_runtime.h>
#include <cuda_fp16.h>
#include <cstdint>

// ---------------------------------------------------------------------------
// HimpNetAlternative: out = scatter_mean( relu(relu(X@W1+b1)@W2+b2), to_index )
// E=320000, C=256, N=10000
//
// Round 8: fragment-reuse fused kernel. Each warp owns 16 rows x 256 cols.
// Phase-1 accumulators ARE phase-2 A-fragments (bias+relu+pack in registers):
// no M1 smem tile, no ldmatrix, 60KB smem.
// ---------------------------------------------------------------------------

__device__ __half g_wpack[2][65536];   // W fragments, fp16
__device__ int    g_cnt[16384];

// ------------------------------- helpers ----------------------------------

__device__ __forceinline__ uint32_t smem_u32(const void* p) {
    uint32_t a;
    asm("{ .reg .u64 t; cvta.to.shared.u64 t, %1; cvt.u32.u64 %0, t; }"
        : "=r"(a) : "l"(p));
    return a;
}

__device__ __forceinline__ void cpa16(uint32_t s, const void* g) {
    asm volatile("cp.async.cg.shared.global [%0], [%1], 16;" :: "r"(s), "l"(g));
}

__device__ __forceinline__ void mma_f16(float* d, const uint32_t* a,
                                        const uint32_t* b) {
    asm volatile(
        "mma.sync.aligned.m16n8k16.row.col.f32.f16.f16.f32 "
        "{%0,%1,%2,%3}, {%4,%5,%6,%7}, {%8,%9}, {%0,%1,%2,%3};"
        : "+f"(d[0]), "+f"(d[1]), "+f"(d[2]), "+f"(d[3])
        : "r"(a[0]), "r"(a[1]), "r"(a[2]), "r"(a[3]), "r"(b[0]), "r"(b[1]));
}

__device__ __forceinline__ uint32_t h2(float x, float y) {
    __half2 h = __floats2half2_rn(x, y);
    return *(uint32_t*)&h;
}

// --------------------------------- prep -----------------------------------

__global__ void zero_kernel(float4* __restrict__ out, int n4,
                            int* __restrict__ cnt, int n_nodes) {
    int i = blockIdx.x * blockDim.x + threadIdx.x;
    if (i < n4)      out[i] = make_float4(0.f, 0.f, 0.f, 0.f);
    if (i < n_nodes) cnt[i] = 0;
}

// Pack W[k][n] (256x256 row-major, fp32) into fp16 mma-B fragment order:
// [s(16)][nb(2)][f2(8)][lane(32)][fp(2)][i(4)].  Both layers, one launch.
__global__ void pack_w_kernel(const float* __restrict__ Wa,
                              const float* __restrict__ Wb,
                              __half* __restrict__ dst) {
    int o = blockIdx.x * 256 + threadIdx.x;      // 131072 halves total
    const float* W = (o < 65536) ? Wa : Wb;
    int ol = o & 65535;
    int i    = ol & 3;
    int fp   = (ol >> 2) & 1;
    int lane = (ol >> 3) & 31;
    int f2   = (ol >> 8) & 7;
    int nb   = (ol >> 11) & 1;
    int s    = ol >> 12;
    int f = f2 * 2 + fp;
    int n = nb * 128 + f * 8 + (lane >> 2);
    int k = s * 16 + (lane & 3) * 2 + (i & 1) + (i >> 1) * 8;
    dst[o] = __float2half_rn(W[k * 256 + n]);
}

__global__ void finalize_kernel(float* __restrict__ out,
                                const int* __restrict__ cnt, int total) {
    int i = blockIdx.x * blockDim.x + threadIdx.x;
    if (i >= total) return;
    int c = cnt[i >> 8];
    float v = out[i];
    out[i] = (c > 0) ? v / (float)c : 0.0f;
}

// ------------------------------ fused kernel -------------------------------
// smem: Af (fp32 X tiles, 3 stages, pitch 24)   36864 B
//       Bs (W fragments, 3 stages, 4096 halves) 24576 B
static constexpr int AF_PITCH = 24;                   // floats
static constexpr int AF_STAGE = 128 * AF_PITCH;       // floats
static constexpr int BS_STAGE = 4096;                 // halves
static constexpr size_t SHMEM_BYTES = 3 * AF_STAGE * 4 + 3 * BS_STAGE * 2;

__global__ void __launch_bounds__(256, 1)
fused_mlp_kernel(const float* __restrict__ X,
                 const __half* __restrict__ Wp1, const __half* __restrict__ Wp2,
                 const float* __restrict__ b1, const float* __restrict__ b2,
                 float* __restrict__ out, const int* __restrict__ ti,
                 int* __restrict__ cnt) {
    extern __shared__ float smem[];
    float*  Af = smem;
    __half* Bs = (__half*)(smem + 3 * AF_STAGE);

    const int tid  = threadIdx.x;
    const int lane = tid & 31, wid = tid >> 5;     // warp owns rows wid*16..+16
    const int gid = lane >> 2, tig = lane & 3;
    const int brow = blockIdx.x * 128;

    const float* Asrc = X + (size_t)brow * 256;

    // acc: 32 n-tiles x 4 regs; reused by both phases.  ah: phase-2 A frags.
    float    acc[32][4];
    uint32_t ah[16][4];

#pragma unroll
    for (int j = 0; j < 32; j++)
#pragma unroll
        for (int q = 0; q < 4; q++) acc[j][q] = 0.0f;

    const int arow = tid >> 1, ac4 = (tid & 1) * 2;      // A: 2 float4 / thread

    auto loadA = [&](int c, int st) {
#pragma unroll
        for (int i = 0; i < 2; i++) {
            int c4 = ac4 + i;
            cpa16(smem_u32(&Af[st * AF_STAGE + arow * AF_PITCH + c4 * 4]),
                  Asrc + (size_t)arow * 256 + c * 16 + c4 * 4);
        }
    };
    auto loadB = [&](const __half* Wp, int c, int st) {
#pragma unroll
        for (int i = 0; i < 2; i++) {
            int f = tid + i * 256;
            cpa16(smem_u32(&Bs[st * BS_STAGE + f * 8]),
                  Wp + (size_t)c * 4096 + f * 8);
        }
    };

    // ================= phase 1: acc = X @ W1 (warp: 16 rows x 256 cols) ====
    loadA(0, 0); loadB(Wp1, 0, 0);
    asm volatile("cp.async.commit_group;" ::: "memory");
    loadA(1, 1); loadB(Wp1, 1, 1);
    asm volatile("cp.async.commit_group;" ::: "memory");

    // histogram for this CTA's 128 edges, hidden under the cp.async fill
    if (tid < 128) atomicAdd(&cnt[ti[brow + tid]], 1);

    for (int c = 0; c < 16; c++) {
        const int st = c % 3;
        if (c < 15) asm volatile("cp.async.wait_group 1;" ::: "memory");
        else        asm volatile("cp.async.wait_group 0;" ::: "memory");
        __syncthreads();
        if (c + 2 < 16) {
            const int ls = (c + 2) % 3;
            loadA(c + 2, ls); loadB(Wp1, c + 2, ls);
            asm volatile("cp.async.commit_group;" ::: "memory");
        }
        // A fragments: rows wid*16+gid(+8), k = c*16 + tig*2 (+8)
        const float* ar = Af + st * AF_STAGE + (wid * 16 + gid) * AF_PITCH + tig * 2;
        float2 v0 = *(const float2*)(ar);
        float2 v1 = *(const float2*)(ar + 8 * AF_PITCH);
        float2 v2 = *(const float2*)(ar + 8);
        float2 v3 = *(const float2*)(ar + 8 * AF_PITCH + 8);
        uint32_t a[4];
        a[0] = h2(v0.x, v0.y);
        a[1] = h2(v1.x, v1.y);
        a[2] = h2(v2.x, v2.y);
        a[3] = h2(v3.x, v3.y);
        const __half* bs = &Bs[st * BS_STAGE];
#pragma unroll
        for (int t2 = 0; t2 < 16; t2++) {
            uint4 v = *(const uint4*)(bs + t2 * 256 + lane * 8);
            uint32_t b0[2] = {v.x, v.y}, b1f[2] = {v.z, v.w};
            mma_f16(acc[t2 * 2],     a, b0);
            mma_f16(acc[t2 * 2 + 1], a, b1f);
        }
    }
    __syncthreads();   // all warps done reading stage 0 before phase-2 prefetch

    // ---- phase-1 epilogue in registers: relu(acc + b1) -> ah fragments ----
    // ah[c][0] = (row gid,   k=c*16+tig*2,+1) = acc[2c]  d0,d1
    // ah[c][1] = (row gid+8, k low)           = acc[2c]  d2,d3
    // ah[c][2] = (row gid,   k high)          = acc[2c+1]d0,d1
    // ah[c][3] = (row gid+8, k high)          = acc[2c+1]d2,d3
#pragma unroll
    for (int c = 0; c < 16; c++) {
        const int j0 = c * 2, j1 = j0 + 1;
        float2 bv0 = *(const float2*)(b1 + j0 * 8 + tig * 2);
        float2 bv1 = *(const float2*)(b1 + j1 * 8 + tig * 2);
        ah[c][0] = h2(fmaxf(acc[j0][0] + bv0.x, 0.f),
                      fmaxf(acc[j0][1] + bv0.y, 0.f));
        ah[c][1] = h2(fmaxf(acc[j0][2] + bv0.x, 0.f),
                      fmaxf(acc[j0][3] + bv0.y, 0.f));
        ah[c][2] = h2(fmaxf(acc[j1][0] + bv1.x, 0.f),
                      fmaxf(acc[j1][1] + bv1.y, 0.f));
        ah[c][3] = h2(fmaxf(acc[j1][2] + bv1.x, 0.f),
                      fmaxf(acc[j1][3] + bv1.y, 0.f));
    }

#pragma unroll
    for (int j = 0; j < 32; j++)
#pragma unroll
        for (int q = 0; q < 4; q++) acc[j][q] = 0.0f;

    // ================= phase 2: acc = m1 @ W2 (A from registers) ===========
    loadB(Wp2, 0, 0);
    asm volatile("cp.async.commit_group;" ::: "memory");
    loadB(Wp2, 1, 1);
    asm volatile("cp.async.commit_group;" ::: "memory");

    for (int c = 0; c < 16; c++) {
        const int st = c % 3;
        if (c < 15) asm volatile("cp.async.wait_group 1;" ::: "memory");
        else        asm volatile("cp.async.wait_group 0;" ::: "memory");
        __syncthreads();
        if (c + 2 < 16) {
            loadB(Wp2, c + 2, (c + 2) % 3);
            asm volatile("cp.async.commit_group;" ::: "memory");
        }
        const __half* bs = &Bs[st * BS_STAGE];
#pragma unroll
        for (int t2 = 0; t2 < 16; t2++) {
            uint4 v = *(const uint4*)(bs + t2 * 256 + lane * 8);
            uint32_t b0[2] = {v.x, v.y}, b1f[2] = {v.z, v.w};
            mma_f16(acc[t2 * 2],     ah[c], b0);
            mma_f16(acc[t2 * 2 + 1], ah[c], b1f);
        }
    }

    // ---- phase-2 epilogue: relu(acc + b2), zero-skipped RED scatter ----
    const int r0 = brow + wid * 16 + gid, r1 = r0 + 8;
    const int n0 = ti[r0], n1 = ti[r1];
    float* p0 = out + (size_t)n0 * 256 + tig * 2;
    float* p1 = out + (size_t)n1 * 256 + tig * 2;
#pragma unroll
    for (int j = 0; j < 32; j++) {
        float2 bv = *(const float2*)(b2 + j * 8 + tig * 2);
        float v;
        v = acc[j][0] + bv.x; if (v > 0.f) atomicAdd(p0 + j * 8,     v);
        v = acc[j][1] + bv.y; if (v > 0.f) atomicAdd(p0 + j * 8 + 1, v);
        v = acc[j][2] + bv.x; if (v > 0.f) atomicAdd(p1 + j * 8,     v);
        v = acc[j][3] + bv.y; if (v > 0.f) atomicAdd(p1 + j * 8 + 1, v);
    }
}

// ------------------------------ kernel_launch -----------------------------

extern "C" void kernel_launch(void* const* d_in, const int* in_sizes, int n_in,
                              void* d_out, int out_size) {
    const float* X  = (const float*)d_in[0];
    const int*   ti = (const int*)d_in[1];
    int wi = 2;
    if (n_in >= 7 && in_sizes[2] <= 4) wi = 3;
    const float* W1 = (const float*)d_in[wi];
    const float* b1 = (const float*)d_in[wi + 1];
    const float* W2 = (const float*)d_in[wi + 2];
    const float* b2 = (const float*)d_in[wi + 3];

    const int E = in_sizes[1];        // 320000
    const int N = out_size / 256;     // 10000
    float* out = (float*)d_out;

    __half* wp0;  int* cnt;
    cudaGetSymbolAddress((void**)&wp0, g_wpack);
    cudaGetSymbolAddress((void**)&cnt, g_cnt);
    __half* wp1 = wp0 + 65536;

    cudaFuncSetAttribute(fused_mlp_kernel,
                         cudaFuncAttributeMaxDynamicSharedMemorySize,
                         (int)SHMEM_BYTES);

    pack_w_kernel<<<512, 256>>>(W1, W2, wp0);
    zero_kernel<<<(out_size / 4 + 255) / 256, 256>>>((float4*)out, out_size / 4,
                                                     cnt, N);

    fused_mlp_kernel<<<E / 128, 256, SHMEM_BYTES>>>(X, wp0, wp1, b1, b2, out,
                                                    ti, cnt);
    finalize_kernel<<<(out_size + 255) / 256, 256>>>(out, cnt, out_size);
}

// round 9
// speedup vs baseline: 1.0463x; 1.0463x over previous
#include <cuda_runtime.h>
#include <cuda_fp16.h>
#include <cstdint>

// ---------------------------------------------------------------------------
// HimpNetAlternative: out = scatter_mean( relu(relu(X@W1+b1)@W2+b2), to_index )
// E=320000, C=256, N=10000
//
// Round 9: R7 GEMM core (best: 407us) + consolidation:
//   - finalize vectorized (float4/thread)
//   - pack_w + zero merged into one prep launch
//   - epilogue ti[] loads hoisted into the prologue shadow
// ---------------------------------------------------------------------------

__device__ __half g_wpack[2][65536];   // W fragments, fp16
__device__ int    g_cnt[16384];

// ------------------------------- helpers ----------------------------------

__device__ __forceinline__ uint32_t smem_u32(const void* p) {
    uint32_t a;
    asm("{ .reg .u64 t; cvta.to.shared.u64 t, %1; cvt.u32.u64 %0, t; }"
        : "=r"(a) : "l"(p));
    return a;
}

__device__ __forceinline__ void cpa16(uint32_t s, const void* g) {
    asm volatile("cp.async.cg.shared.global [%0], [%1], 16;" :: "r"(s), "l"(g));
}

__device__ __forceinline__ void ldmx4(uint32_t* r, uint32_t addr) {
    asm volatile("ldmatrix.sync.aligned.m8n8.x4.shared.b16 {%0,%1,%2,%3}, [%4];"
                 : "=r"(r[0]), "=r"(r[1]), "=r"(r[2]), "=r"(r[3]) : "r"(addr));
}

__device__ __forceinline__ void mma_f16(float* d, const uint32_t* a,
                                        const uint32_t* b) {
    asm volatile(
        "mma.sync.aligned.m16n8k16.row.col.f32.f16.f16.f32 "
        "{%0,%1,%2,%3}, {%4,%5,%6,%7}, {%8,%9}, {%0,%1,%2,%3};"
        : "+f"(d[0]), "+f"(d[1]), "+f"(d[2]), "+f"(d[3])
        : "r"(a[0]), "r"(a[1]), "r"(a[2]), "r"(a[3]), "r"(b[0]), "r"(b[1]));
}

__device__ __forceinline__ uint32_t h2(float x, float y) {
    __half2 h = __floats2half2_rn(x, y);
    return *(uint32_t*)&h;
}

// --------------------------------- prep -----------------------------------
// Merged prep: blocks [0,512) pack both weight matrices into fragment order;
// blocks [512, 512+n4blocks) zero the output sums; counts zeroed alongside.
__global__ void prep_kernel(const float* __restrict__ Wa,
                            const float* __restrict__ Wb,
                            __half* __restrict__ dst,
                            float4* __restrict__ out, int n4,
                            int* __restrict__ cnt, int n_nodes) {
    int blk = blockIdx.x;
    if (blk < 512) {
        int o = blk * 256 + threadIdx.x;      // 131072 halves total
        const float* W = (o < 65536) ? Wa : Wb;
        int ol = o & 65535;
        int i    = ol & 3;
        int fp   = (ol >> 2) & 1;
        int lane = (ol >> 3) & 31;
        int f2   = (ol >> 8) & 7;
        int nb   = (ol >> 11) & 1;
        int s    = ol >> 12;
        int f = f2 * 2 + fp;
        int n = nb * 128 + f * 8 + (lane >> 2);
        int k = s * 16 + (lane & 3) * 2 + (i & 1) + (i >> 1) * 8;
        dst[o] = __float2half_rn(W[k * 256 + n]);
    } else {
        int i = (blk - 512) * 256 + threadIdx.x;
        if (i < n4)      out[i] = make_float4(0.f, 0.f, 0.f, 0.f);
        if (i < n_nodes) cnt[i] = 0;
    }
}

__global__ void finalize_kernel(float4* __restrict__ out,
                                const int* __restrict__ cnt, int n4) {
    int i = blockIdx.x * blockDim.x + threadIdx.x;
    if (i >= n4) return;
    int c = cnt[i >> 6];               // 64 float4 per 256-col row
    float4 v = out[i];
    if (c > 0) {
        float inv = 1.0f / (float)c;
        v.x *= inv; v.y *= inv; v.z *= inv; v.w *= inv;
    } else {
        v = make_float4(0.f, 0.f, 0.f, 0.f);
    }
    out[i] = v;
}

// ------------------------------ fused kernel -------------------------------
// smem: Af (fp32 X tiles, 3 stages, pitch 24)   3*12288 B
//       Bs (W fragments, 3 stages, 4096 halves) 3*8192 B
//       M1 (fp16 tile, 128 x pitch 264)         67584 B
static constexpr int AF_PITCH = 24;                   // floats
static constexpr int AF_STAGE = 128 * AF_PITCH;       // floats
static constexpr int BS_STAGE = 4096;                 // halves
static constexpr int M1_PITCH = 264;                  // halves
static constexpr size_t SHMEM_BYTES =
    3 * AF_STAGE * 4 + 3 * BS_STAGE * 2 + 128 * M1_PITCH * 2;   // 129024

__global__ void __launch_bounds__(256)
fused_mlp_kernel(const float* __restrict__ X,
                 const __half* __restrict__ Wp1, const __half* __restrict__ Wp2,
                 const float* __restrict__ b1, const float* __restrict__ b2,
                 float* __restrict__ out, const int* __restrict__ ti,
                 int* __restrict__ cnt) {
    extern __shared__ float smem[];
    float*  Af  = smem;
    __half* Bs  = (__half*)(smem + 3 * AF_STAGE);
    __half* M1  = Bs + 3 * BS_STAGE;

    const int tid  = threadIdx.x;
    const int lane = tid & 31, wid = tid >> 5;
    const int wm = wid & 3, wn = wid >> 2;       // 4M x 2N warps
    const int gid = lane >> 2, tig = lane & 3;
    const int brow = blockIdx.x * 128;

    const float* Asrc = X + (size_t)brow * 256;

    float acc[2][16][4];
#pragma unroll
    for (int m = 0; m < 2; m++)
#pragma unroll
        for (int j = 0; j < 16; j++)
#pragma unroll
            for (int q = 0; q < 4; q++) acc[m][j][q] = 0.0f;

    const int arow = tid >> 1, ac4 = (tid & 1) * 2;      // A: 2 float4 / thread

    auto loadA = [&](int c, int st) {
#pragma unroll
        for (int i = 0; i < 2; i++) {
            int c4 = ac4 + i;
            cpa16(smem_u32(&Af[st * AF_STAGE + arow * AF_PITCH + c4 * 4]),
                  Asrc + (size_t)arow * 256 + c * 16 + c4 * 4);
        }
    };
    auto loadB = [&](const __half* Wp, int c, int st) {
#pragma unroll
        for (int i = 0; i < 2; i++) {
            int f = tid + i * 256;
            cpa16(smem_u32(&Bs[st * BS_STAGE + f * 8]),
                  Wp + (size_t)c * 4096 + f * 8);
        }
    };
    auto loadBfrags = [&](int st, uint32_t (*b)[2]) {
        const __half* bs = &Bs[st * BS_STAGE + wn * 2048];
#pragma unroll
        for (int j2 = 0; j2 < 8; j2++) {
            uint4 v = *(const uint4*)(bs + j2 * 256 + lane * 8);
            b[j2 * 2][0] = v.x;     b[j2 * 2][1] = v.y;
            b[j2 * 2 + 1][0] = v.z; b[j2 * 2 + 1][1] = v.w;
        }
    };

    // ================= phase 1: acc = X @ W1 =================
    loadA(0, 0); loadB(Wp1, 0, 0);
    asm volatile("cp.async.commit_group;" ::: "memory");
    loadA(1, 1); loadB(Wp1, 1, 1);
    asm volatile("cp.async.commit_group;" ::: "memory");

    // hidden under the cp.async fill: histogram + epilogue node prefetch
    if (tid < 128) atomicAdd(&cnt[ti[brow + tid]], 1);
    int nodes[2][2];
#pragma unroll
    for (int mf = 0; mf < 2; mf++) {
        const int r = brow + wm * 32 + mf * 16 + gid;
        nodes[mf][0] = ti[r];
        nodes[mf][1] = ti[r + 8];
    }

    for (int c = 0; c < 16; c++) {
        const int st = c % 3;
        if (c < 15) asm volatile("cp.async.wait_group 1;" ::: "memory");
        else        asm volatile("cp.async.wait_group 0;" ::: "memory");
        __syncthreads();
        if (c + 2 < 16) {
            const int ls = (c + 2) % 3;
            loadA(c + 2, ls); loadB(Wp1, c + 2, ls);
            asm volatile("cp.async.commit_group;" ::: "memory");
        }
        const float* as = Af + st * AF_STAGE + wm * 32 * AF_PITCH;
        uint32_t a[2][4];
#pragma unroll
        for (int mf = 0; mf < 2; mf++) {
            const float* ar = as + (mf * 16 + gid) * AF_PITCH + tig * 2;
            float2 v0 = *(const float2*)(ar);
            float2 v1 = *(const float2*)(ar + 8 * AF_PITCH);
            float2 v2 = *(const float2*)(ar + 8);
            float2 v3 = *(const float2*)(ar + 8 * AF_PITCH + 8);
            a[mf][0] = h2(v0.x, v0.y);
            a[mf][1] = h2(v1.x, v1.y);
            a[mf][2] = h2(v2.x, v2.y);
            a[mf][3] = h2(v3.x, v3.y);
        }
        uint32_t b[16][2];
        loadBfrags(st, b);
#pragma unroll
        for (int mf = 0; mf < 2; mf++)
#pragma unroll
            for (int j = 0; j < 16; j++)
                mma_f16(acc[mf][j], a[mf], b[j]);
    }

    // ---- phase 1 epilogue: relu(acc + b1) -> fp16 M1 tile ----
#pragma unroll
    for (int mf = 0; mf < 2; mf++) {
        const int r0 = wm * 32 + mf * 16 + gid, r1 = r0 + 8;
#pragma unroll
        for (int j = 0; j < 16; j++) {
            const int col = wn * 128 + j * 8 + tig * 2;
            float2 bv = *(const float2*)(b1 + col);
            *(uint32_t*)&M1[r0 * M1_PITCH + col] =
                h2(fmaxf(acc[mf][j][0] + bv.x, 0.f),
                   fmaxf(acc[mf][j][1] + bv.y, 0.f));
            *(uint32_t*)&M1[r1 * M1_PITCH + col] =
                h2(fmaxf(acc[mf][j][2] + bv.x, 0.f),
                   fmaxf(acc[mf][j][3] + bv.y, 0.f));
        }
    }

#pragma unroll
    for (int m = 0; m < 2; m++)
#pragma unroll
        for (int j = 0; j < 16; j++)
#pragma unroll
            for (int q = 0; q < 4; q++) acc[m][j][q] = 0.0f;

    // ================= phase 2: M1 @ W2, atomic scatter =================
    loadB(Wp2, 0, 0);
    asm volatile("cp.async.commit_group;" ::: "memory");
    loadB(Wp2, 1, 1);
    asm volatile("cp.async.commit_group;" ::: "memory");

    const uint32_t m1base = smem_u32(
        &M1[(wm * 32 + (lane & 15)) * M1_PITCH + (lane >> 4) * 8]);

    for (int c = 0; c < 16; c++) {
        const int st = c % 3;
        if (c < 15) asm volatile("cp.async.wait_group 1;" ::: "memory");
        else        asm volatile("cp.async.wait_group 0;" ::: "memory");
        __syncthreads();   // iter 0 also publishes M1 to all warps
        if (c + 2 < 16) {
            loadB(Wp2, c + 2, (c + 2) % 3);
            asm volatile("cp.async.commit_group;" ::: "memory");
        }
        uint32_t a[2][4];
#pragma unroll
        for (int mf = 0; mf < 2; mf++)
            ldmx4(a[mf], m1base + (uint32_t)((mf * 16 * M1_PITCH + c * 16) * 2));
        uint32_t b[16][2];
        loadBfrags(st, b);
#pragma unroll
        for (int mf = 0; mf < 2; mf++)
#pragma unroll
            for (int j = 0; j < 16; j++)
                mma_f16(acc[mf][j], a[mf], b[j]);
    }

    // ---- phase 2 epilogue: relu(acc + b2), zero-skipped RED scatter ----
#pragma unroll
    for (int mf = 0; mf < 2; mf++) {
        float* p0 = out + (size_t)nodes[mf][0] * 256 + wn * 128 + tig * 2;
        float* p1 = out + (size_t)nodes[mf][1] * 256 + wn * 128 + tig * 2;
#pragma unroll
        for (int j = 0; j < 16; j++) {
            const int col = wn * 128 + j * 8 + tig * 2;
            float2 bv = *(const float2*)(b2 + col);
            float v;
            v = acc[mf][j][0] + bv.x; if (v > 0.f) atomicAdd(p0 + j * 8,     v);
            v = acc[mf][j][1] + bv.y; if (v > 0.f) atomicAdd(p0 + j * 8 + 1, v);
            v = acc[mf][j][2] + bv.x; if (v > 0.f) atomicAdd(p1 + j * 8,     v);
            v = acc[mf][j][3] + bv.y; if (v > 0.f) atomicAdd(p1 + j * 8 + 1, v);
        }
    }
}

// ------------------------------ kernel_launch -----------------------------

extern "C" void kernel_launch(void* const* d_in, const int* in_sizes, int n_in,
                              void* d_out, int out_size) {
    const float* X  = (const float*)d_in[0];
    const int*   ti = (const int*)d_in[1];
    int wi = 2;
    if (n_in >= 7 && in_sizes[2] <= 4) wi = 3;
    const float* W1 = (const float*)d_in[wi];
    const float* b1 = (const float*)d_in[wi + 1];
    const float* W2 = (const float*)d_in[wi + 2];
    const float* b2 = (const float*)d_in[wi + 3];

    const int E = in_sizes[1];        // 320000
    const int N = out_size / 256;     // 10000
    float* out = (float*)d_out;

    __half* wp0;  int* cnt;
    cudaGetSymbolAddress((void**)&wp0, g_wpack);
    cudaGetSymbolAddress((void**)&cnt, g_cnt);
    __half* wp1 = wp0 + 65536;

    cudaFuncSetAttribute(fused_mlp_kernel,
                         cudaFuncAttributeMaxDynamicSharedMemorySize,
                         (int)SHMEM_BYTES);

    const int n4 = out_size / 4;
    const int zblocks = (n4 + 255) / 256;
    prep_kernel<<<512 + zblocks, 256>>>(W1, W2, wp0, (float4*)out, n4, cnt, N);

    fused_mlp_kernel<<<E / 128, 256, SHMEM_BYTES>>>(X, wp0, wp1, b1, b2, out,
                                                    ti, cnt);
    finalize_kernel<<<(n4 + 255) / 256, 256>>>((float4*)out, cnt, n4);
}

// round 10
// speedup vs baseline: 1.3042x; 1.2465x over previous
#include <cuda_runtime.h>
#include <cuda_fp16.h>
#include <cstdint>

// ---------------------------------------------------------------------------
// HimpNetAlternative: out = scatter_mean( relu(relu(X@W1+b1)@W2+b2), to_index )
// E=320000, C=256, N=10000
//
// Round 10: 512-thread CTA (16 warps, 4M x 4N, warp tile 32x64) to double
// warps/SMSP 2->4 — the R9 cycle model shows the tensor pipe only ~40% busy
// (latency-bound, not pipe-bound). Same 128x256 tile, smem, pipeline as R9.
// ---------------------------------------------------------------------------

__device__ __half g_wpack[2][65536];   // W fragments, fp16
__device__ int    g_cnt[16384];

// ------------------------------- helpers ----------------------------------

__device__ __forceinline__ uint32_t smem_u32(const void* p) {
    uint32_t a;
    asm("{ .reg .u64 t; cvta.to.shared.u64 t, %1; cvt.u32.u64 %0, t; }"
        : "=r"(a) : "l"(p));
    return a;
}

__device__ __forceinline__ void cpa16(uint32_t s, const void* g) {
    asm volatile("cp.async.cg.shared.global [%0], [%1], 16;" :: "r"(s), "l"(g));
}

__device__ __forceinline__ void ldmx4(uint32_t* r, uint32_t addr) {
    asm volatile("ldmatrix.sync.aligned.m8n8.x4.shared.b16 {%0,%1,%2,%3}, [%4];"
                 : "=r"(r[0]), "=r"(r[1]), "=r"(r[2]), "=r"(r[3]) : "r"(addr));
}

__device__ __forceinline__ void mma_f16(float* d, const uint32_t* a,
                                        const uint32_t* b) {
    asm volatile(
        "mma.sync.aligned.m16n8k16.row.col.f32.f16.f16.f32 "
        "{%0,%1,%2,%3}, {%4,%5,%6,%7}, {%8,%9}, {%0,%1,%2,%3};"
        : "+f"(d[0]), "+f"(d[1]), "+f"(d[2]), "+f"(d[3])
        : "r"(a[0]), "r"(a[1]), "r"(a[2]), "r"(a[3]), "r"(b[0]), "r"(b[1]));
}

__device__ __forceinline__ uint32_t h2(float x, float y) {
    __half2 h = __floats2half2_rn(x, y);
    return *(uint32_t*)&h;
}

// --------------------------------- prep -----------------------------------
__global__ void prep_kernel(const float* __restrict__ Wa,
                            const float* __restrict__ Wb,
                            __half* __restrict__ dst,
                            float4* __restrict__ out, int n4,
                            int* __restrict__ cnt, int n_nodes) {
    int blk = blockIdx.x;
    if (blk < 512) {
        int o = blk * 256 + threadIdx.x;      // 131072 halves total
        const float* W = (o < 65536) ? Wa : Wb;
        int ol = o & 65535;
        int i    = ol & 3;
        int fp   = (ol >> 2) & 1;
        int lane = (ol >> 3) & 31;
        int f2   = (ol >> 8) & 7;
        int nb   = (ol >> 11) & 1;
        int s    = ol >> 12;
        int f = f2 * 2 + fp;
        int n = nb * 128 + f * 8 + (lane >> 2);
        int k = s * 16 + (lane & 3) * 2 + (i & 1) + (i >> 1) * 8;
        dst[o] = __float2half_rn(W[k * 256 + n]);
    } else {
        int i = (blk - 512) * 256 + threadIdx.x;
        if (i < n4)      out[i] = make_float4(0.f, 0.f, 0.f, 0.f);
        if (i < n_nodes) cnt[i] = 0;
    }
}

__global__ void finalize_kernel(float4* __restrict__ out,
                                const int* __restrict__ cnt, int n4) {
    int i = blockIdx.x * blockDim.x + threadIdx.x;
    if (i >= n4) return;
    int c = cnt[i >> 6];               // 64 float4 per 256-col row
    float4 v = out[i];
    if (c > 0) {
        float inv = 1.0f / (float)c;
        v.x *= inv; v.y *= inv; v.z *= inv; v.w *= inv;
    } else {
        v = make_float4(0.f, 0.f, 0.f, 0.f);
    }
    out[i] = v;
}

// ------------------------------ fused kernel -------------------------------
static constexpr int AF_PITCH = 24;                   // floats
static constexpr int AF_STAGE = 128 * AF_PITCH;       // floats
static constexpr int BS_STAGE = 4096;                 // halves
static constexpr int M1_PITCH = 264;                  // halves
static constexpr size_t SHMEM_BYTES =
    3 * AF_STAGE * 4 + 3 * BS_STAGE * 2 + 128 * M1_PITCH * 2;   // 129024

__global__ void __launch_bounds__(512, 1)
fused_mlp_kernel(const float* __restrict__ X,
                 const __half* __restrict__ Wp1, const __half* __restrict__ Wp2,
                 const float* __restrict__ b1, const float* __restrict__ b2,
                 float* __restrict__ out, const int* __restrict__ ti,
                 int* __restrict__ cnt) {
    extern __shared__ float smem[];
    float*  Af  = smem;
    __half* Bs  = (__half*)(smem + 3 * AF_STAGE);
    __half* M1  = Bs + 3 * BS_STAGE;

    const int tid  = threadIdx.x;
    const int lane = tid & 31, wid = tid >> 5;
    const int wm = wid & 3, wn = wid >> 2;       // 4M x 4N warps, tile 32x64
    const int gid = lane >> 2, tig = lane & 3;
    const int brow = blockIdx.x * 128;

    const float* Asrc = X + (size_t)brow * 256;

    float acc[2][8][4];
#pragma unroll
    for (int m = 0; m < 2; m++)
#pragma unroll
        for (int j = 0; j < 8; j++)
#pragma unroll
            for (int q = 0; q < 4; q++) acc[m][j][q] = 0.0f;

    // loads: one cp.async per thread per tile (512 float4 each)
    const int arow = tid >> 2, ac4 = tid & 3;

    auto loadA = [&](int c, int st) {
        cpa16(smem_u32(&Af[st * AF_STAGE + arow * AF_PITCH + ac4 * 4]),
              Asrc + (size_t)arow * 256 + c * 16 + ac4 * 4);
    };
    auto loadB = [&](const __half* Wp, int c, int st) {
        cpa16(smem_u32(&Bs[st * BS_STAGE + tid * 8]),
              Wp + (size_t)c * 4096 + tid * 8);
    };
    auto loadBfrags = [&](int st, uint32_t (*b)[2]) {
        const __half* bs = &Bs[st * BS_STAGE + wn * 1024];
#pragma unroll
        for (int j2 = 0; j2 < 4; j2++) {
            uint4 v = *(const uint4*)(bs + j2 * 256 + lane * 8);
            b[j2 * 2][0] = v.x;     b[j2 * 2][1] = v.y;
            b[j2 * 2 + 1][0] = v.z; b[j2 * 2 + 1][1] = v.w;
        }
    };

    // ================= phase 1: acc = X @ W1 =================
    loadA(0, 0); loadB(Wp1, 0, 0);
    asm volatile("cp.async.commit_group;" ::: "memory");
    loadA(1, 1); loadB(Wp1, 1, 1);
    asm volatile("cp.async.commit_group;" ::: "memory");

    // hidden under the cp.async fill: histogram + epilogue node prefetch
    if (tid < 128) atomicAdd(&cnt[ti[brow + tid]], 1);
    int nodes[2];
#pragma unroll
    for (int mf = 0; mf < 2; mf++)
        nodes[mf] = ti[brow + wm * 32 + mf * 16 + gid + ((lane >> 4) ? 0 : 0)];
    // rows r0 = wm*32+mf*16+gid and r1 = r0+8 both needed:
    int nodes8[2];
#pragma unroll
    for (int mf = 0; mf < 2; mf++)
        nodes8[mf] = ti[brow + wm * 32 + mf * 16 + gid + 8];

    for (int c = 0; c < 16; c++) {
        const int st = c % 3;
        if (c < 15) asm volatile("cp.async.wait_group 1;" ::: "memory");
        else        asm volatile("cp.async.wait_group 0;" ::: "memory");
        __syncthreads();
        if (c + 2 < 16) {
            const int ls = (c + 2) % 3;
            loadA(c + 2, ls); loadB(Wp1, c + 2, ls);
            asm volatile("cp.async.commit_group;" ::: "memory");
        }
        const float* as = Af + st * AF_STAGE + wm * 32 * AF_PITCH;
        uint32_t a[2][4];
#pragma unroll
        for (int mf = 0; mf < 2; mf++) {
            const float* ar = as + (mf * 16 + gid) * AF_PITCH + tig * 2;
            float2 v0 = *(const float2*)(ar);
            float2 v1 = *(const float2*)(ar + 8 * AF_PITCH);
            float2 v2 = *(const float2*)(ar + 8);
            float2 v3 = *(const float2*)(ar + 8 * AF_PITCH + 8);
            a[mf][0] = h2(v0.x, v0.y);
            a[mf][1] = h2(v1.x, v1.y);
            a[mf][2] = h2(v2.x, v2.y);
            a[mf][3] = h2(v3.x, v3.y);
        }
        uint32_t b[8][2];
        loadBfrags(st, b);
#pragma unroll
        for (int mf = 0; mf < 2; mf++)
#pragma unroll
            for (int j = 0; j < 8; j++)
                mma_f16(acc[mf][j], a[mf], b[j]);
    }

    // ---- phase 1 epilogue: relu(acc + b1) -> fp16 M1 tile ----
#pragma unroll
    for (int mf = 0; mf < 2; mf++) {
        const int r0 = wm * 32 + mf * 16 + gid, r1 = r0 + 8;
#pragma unroll
        for (int j = 0; j < 8; j++) {
            const int col = wn * 64 + j * 8 + tig * 2;
            float2 bv = *(const float2*)(b1 + col);
            *(uint32_t*)&M1[r0 * M1_PITCH + col] =
                h2(fmaxf(acc[mf][j][0] + bv.x, 0.f),
                   fmaxf(acc[mf][j][1] + bv.y, 0.f));
            *(uint32_t*)&M1[r1 * M1_PITCH + col] =
                h2(fmaxf(acc[mf][j][2] + bv.x, 0.f),
                   fmaxf(acc[mf][j][3] + bv.y, 0.f));
        }
    }

#pragma unroll
    for (int m = 0; m < 2; m++)
#pragma unroll
        for (int j = 0; j < 8; j++)
#pragma unroll
            for (int q = 0; q < 4; q++) acc[m][j][q] = 0.0f;

    // ================= phase 2: M1 @ W2, atomic scatter =================
    loadB(Wp2, 0, 0);
    asm volatile("cp.async.commit_group;" ::: "memory");
    loadB(Wp2, 1, 1);
    asm volatile("cp.async.commit_group;" ::: "memory");

    const uint32_t m1base = smem_u32(
        &M1[(wm * 32 + (lane & 15)) * M1_PITCH + (lane >> 4) * 8]);

    for (int c = 0; c < 16; c++) {
        const int st = c % 3;
        if (c < 15) asm volatile("cp.async.wait_group 1;" ::: "memory");
        else        asm volatile("cp.async.wait_group 0;" ::: "memory");
        __syncthreads();   // iter 0 also publishes M1 to all warps
        if (c + 2 < 16) {
            loadB(Wp2, c + 2, (c + 2) % 3);
            asm volatile("cp.async.commit_group;" ::: "memory");
        }
        uint32_t a[2][4];
#pragma unroll
        for (int mf = 0; mf < 2; mf++)
            ldmx4(a[mf], m1base + (uint32_t)((mf * 16 * M1_PITCH + c * 16) * 2));
        uint32_t b[8][2];
        loadBfrags(st, b);
#pragma unroll
        for (int mf = 0; mf < 2; mf++)
#pragma unroll
            for (int j = 0; j < 8; j++)
                mma_f16(acc[mf][j], a[mf], b[j]);
    }

    // ---- phase 2 epilogue: relu(acc + b2), zero-skipped RED scatter ----
#pragma unroll
    for (int mf = 0; mf < 2; mf++) {
        float* p0 = out + (size_t)nodes[mf]  * 256 + wn * 64 + tig * 2;
        float* p1 = out + (size_t)nodes8[mf] * 256 + wn * 64 + tig * 2;
#pragma unroll
        for (int j = 0; j < 8; j++) {
            const int col = wn * 64 + j * 8 + tig * 2;
            float2 bv = *(const float2*)(b2 + col);
            float v;
            v = acc[mf][j][0] + bv.x; if (v > 0.f) atomicAdd(p0 + j * 8,     v);
            v = acc[mf][j][1] + bv.y; if (v > 0.f) atomicAdd(p0 + j * 8 + 1, v);
            v = acc[mf][j][2] + bv.x; if (v > 0.f) atomicAdd(p1 + j * 8,     v);
            v = acc[mf][j][3] + bv.y; if (v > 0.f) atomicAdd(p1 + j * 8 + 1, v);
        }
    }
}

// ------------------------------ kernel_launch -----------------------------

extern "C" void kernel_launch(void* const* d_in, const int* in_sizes, int n_in,
                              void* d_out, int out_size) {
    const float* X  = (const float*)d_in[0];
    const int*   ti = (const int*)d_in[1];
    int wi = 2;
    if (n_in >= 7 && in_sizes[2] <= 4) wi = 3;
    const float* W1 = (const float*)d_in[wi];
    const float* b1 = (const float*)d_in[wi + 1];
    const float* W2 = (const float*)d_in[wi + 2];
    const float* b2 = (const float*)d_in[wi + 3];

    const int E = in_sizes[1];        // 320000
    const int N = out_size / 256;     // 10000
    float* out = (float*)d_out;

    __half* wp0;  int* cnt;
    cudaGetSymbolAddress((void**)&wp0, g_wpack);
    cudaGetSymbolAddress((void**)&cnt, g_cnt);
    __half* wp1 = wp0 + 65536;

    cudaFuncSetAttribute(fused_mlp_kernel,
                         cudaFuncAttributeMaxDynamicSharedMemorySize,
                         (int)SHMEM_BYTES);

    const int n4 = out_size / 4;
    const int zblocks = (n4 + 255) / 256;
    prep_kernel<<<512 + zblocks, 256>>>(W1, W2, wp0, (float4*)out, n4, cnt, N);

    fused_mlp_kernel<<<E / 128, 512, SHMEM_BYTES>>>(X, wp0, wp1, b1, b2, out,
                                                    ti, cnt);
    finalize_kernel<<<(n4 + 255) / 256, 256>>>((float4*)out, cnt, n4);
}